// round 1
// baseline (speedup 1.0000x reference)
#include <cuda_runtime.h>

// Problem constants (fixed shapes from setup_inputs)
#define HH 128
#define WW 256
#define HWP 32768      // H*W
#define CC 64
#define BB 2
#define KK 16

// ---------------- scratch (static device arrays; no allocation) -------------
// image order for tmp/buf: 0=left b0, 1=left b1, 2=right b0, 3=right b1
__device__ float g_tmp[4 * CC * HWP];     // after conv1+lrelu
__device__ float g_buf[4 * CC * HWP];     // after conv2+residual (buf_l, buf_r)
__device__ float g_Q[BB * HWP * CC];      // pixel-major (b, p, c)
__device__ float g_S[BB * HWP * CC];
__device__ float g_R[BB * HWP * CC];
__device__ float g_battn[BB * HWP * CC];  // attention output, pixel-major

// ---------------- packed f32x2 helpers --------------------------------------
__device__ __forceinline__ unsigned long long pk2(float lo, float hi) {
    unsigned long long r;
    asm("mov.b64 %0, {%1, %2};" : "=l"(r) : "f"(lo), "f"(hi));
    return r;
}
__device__ __forceinline__ void upk2(unsigned long long v, float& lo, float& hi) {
    asm("mov.b64 {%0, %1}, %2;" : "=f"(lo), "=f"(hi) : "l"(v));
}
__device__ __forceinline__ unsigned long long fma2(unsigned long long a,
                                                   unsigned long long b,
                                                   unsigned long long c) {
    unsigned long long d;
    asm("fma.rn.f32x2 %0, %1, %2, %3;" : "=l"(d) : "l"(a), "l"(b), "l"(c));
    return d;
}

// ---------------- conv 3x3 (pad=1), C=64 -> C=64 ----------------------------
// MODE 0: in = x_left/x_right (params), out = g_tmp, apply leaky_relu(0.1)
// MODE 1: in = g_tmp, out = g_buf, add residual x_left/x_right
// Block: 256 threads. Tile: 32(x) x 8(y) pixels, all 64 couts.
// Thread: cg = couts [cg*16, cg*16+16); pixels x in {2*tx2, 2*tx2+1},
//         y in {ty, ty+4}  (2 packed pixel-pairs).
template <int MODE>
__global__ void __launch_bounds__(256) conv3x3_k(const float* __restrict__ xl,
                                                 const float* __restrict__ xr,
                                                 const float* __restrict__ w) {
    __shared__ float tile[10][34];
    __shared__ unsigned long long wsm[576];  // [tap*64 + cout], dup-packed

    const int t = threadIdx.x;
    const int img = blockIdx.z;               // 0..3
    const int gx0 = blockIdx.x * 32;
    const int gy0 = blockIdx.y * 8;

    const float* in;
    if (MODE == 0)
        in = (img < 2) ? (xl + img * CC * HWP) : (xr + (img - 2) * CC * HWP);
    else
        in = g_tmp + img * CC * HWP;

    const int cg  = t >> 6;        // 0..3
    const int q   = t & 63;
    const int tx2 = q & 15;        // x pair index
    const int ty  = q >> 4;        // 0..3

    unsigned long long acc[16][2];
#pragma unroll
    for (int c = 0; c < 16; c++) { acc[c][0] = 0ull; acc[c][1] = 0ull; }

    for (int cin = 0; cin < 64; cin++) {
        __syncthreads();
        // load input tile with halo (zero padding)
        for (int i = t; i < 340; i += 256) {
            int r  = i / 34, cc = i - r * 34;
            int gy = gy0 - 1 + r, gx = gx0 - 1 + cc;
            float v = 0.f;
            if ((unsigned)gy < HH && (unsigned)gx < WW)
                v = in[cin * HWP + gy * WW + gx];
            tile[r][cc] = v;
        }
        // load this cin's weight slice, duplicated-packed
        for (int j = t; j < 576; j += 256) {
            int tap = j >> 6, co = j & 63;
            float wv = w[(co * 64 + cin) * 9 + tap];
            wsm[j] = pk2(wv, wv);
        }
        __syncthreads();

#pragma unroll
        for (int dy = 0; dy < 3; dy++) {
#pragma unroll
            for (int dx = 0; dx < 3; dx++) {
                unsigned long long v0 =
                    pk2(tile[ty + dy][2 * tx2 + dx], tile[ty + dy][2 * tx2 + dx + 1]);
                unsigned long long v1 =
                    pk2(tile[ty + 4 + dy][2 * tx2 + dx], tile[ty + 4 + dy][2 * tx2 + dx + 1]);
                const int wb = (dy * 3 + dx) * 64 + cg * 16;
#pragma unroll
                for (int c = 0; c < 16; c++) {
                    unsigned long long w2 = wsm[wb + c];  // warp-broadcast LDS.64
                    acc[c][0] = fma2(w2, v0, acc[c][0]);
                    acc[c][1] = fma2(w2, v1, acc[c][1]);
                }
            }
        }
    }

    float* out = ((MODE == 0) ? g_tmp : g_buf) + img * CC * HWP;
    const float* res = nullptr;
    if (MODE == 1)
        res = (img < 2) ? (xl + img * CC * HWP) : (xr + (img - 2) * CC * HWP);

#pragma unroll
    for (int c = 0; c < 16; c++) {
        const int co = cg * 16 + c;
#pragma unroll
        for (int r = 0; r < 2; r++) {
            float lo, hi;
            upk2(acc[c][r], lo, hi);
            const int y = gy0 + ty + 4 * r;
            const int x = gx0 + 2 * tx2;
            const int off = co * HWP + y * WW + x;
            if (MODE == 0) {
                lo = lo > 0.f ? lo : 0.1f * lo;
                hi = hi > 0.f ? hi : 0.1f * hi;
            } else {
                float2 rv = *(const float2*)(res + off);
                lo += rv.x; hi += rv.y;
            }
            float2 o; o.x = lo; o.y = hi;
            *(float2*)(out + off) = o;
        }
    }
}

// ---------------- 1x1 conv: channel-major in (g_buf) -> pixel-major out -----
// which: 0 = Q (from left images), 1 = S (right), 2 = R (right)
__global__ void __launch_bounds__(256) conv1x1_k(const float* __restrict__ w,
                                                 const float* __restrict__ bias,
                                                 int which) {
    __shared__ __align__(16) float pool[8320];  // weights (32KB) then reused for staging
    unsigned long long* wsm = (unsigned long long*)pool;  // 4096 entries

    const int t  = threadIdx.x;
    const int b  = blockIdx.y;
    const int p0 = blockIdx.x * 256;
    const int imgidx = (which == 0) ? b : (2 + b);
    const float* in = g_buf + imgidx * CC * HWP;
    float* out = ((which == 0) ? g_Q : (which == 1) ? g_S : g_R) + b * HWP * CC;

    for (int j = t; j < 4096; j += 256) {
        int cin = j >> 6, co = j & 63;
        float wv = w[co * 64 + cin];
        wsm[j] = pk2(wv, wv);  // wsm[cin*64 + co]
    }
    __syncthreads();

    const int cg = t >> 6, q = t & 63;
    unsigned long long acc[16][2];
#pragma unroll
    for (int c = 0; c < 16; c++) { acc[c][0] = 0ull; acc[c][1] = 0ull; }

    for (int cin = 0; cin < 64; cin++) {
        unsigned long long v0 = *(const unsigned long long*)(in + cin * HWP + p0 + 2 * q);
        unsigned long long v1 = *(const unsigned long long*)(in + cin * HWP + p0 + 128 + 2 * q);
        const int wb = cin * 64 + cg * 16;
#pragma unroll
        for (int c = 0; c < 16; c++) {
            unsigned long long w2 = wsm[wb + c];
            acc[c][0] = fma2(w2, v0, acc[c][0]);
            acc[c][1] = fma2(w2, v1, acc[c][1]);
        }
    }

    // transpose-stage through smem, then coalesced pixel-major writes
    float* st = pool;  // 128 px x 65 (padded)
#pragma unroll
    for (int j = 0; j < 2; j++) {
        __syncthreads();
#pragma unroll
        for (int c = 0; c < 16; c++) {
            float lo, hi;
            upk2(acc[c][j], lo, hi);
            st[(2 * q) * 65 + cg * 16 + c]     = lo;
            st[(2 * q + 1) * 65 + cg * 16 + c] = hi;
        }
        __syncthreads();
        for (int i = t; i < 8192; i += 256) {
            int px = i >> 6, co = i & 63;
            out[(p0 + 128 * j + px) * 64 + co] = st[px * 65 + co] + bias[co];
        }
    }
}

// ---------------- attention: warp per pixel ---------------------------------
__global__ void __launch_bounds__(256) attn_k(const int* __restrict__ xxs,
                                              const int* __restrict__ yys,
                                              float* __restrict__ Mout) {
    const int t = threadIdx.x;
    const int lane = t & 31;
    const int p = blockIdx.x * 8 + (t >> 5);  // global pixel (b*HW + pp)
    const int b = p >> 15;                    // HW = 2^15

    int fl = 0;
    if (lane < 16) fl = xxs[p * 16 + lane] * WW + yys[p * 16 + lane];

    const float q0 = g_Q[p * 64 + lane];
    const float q1 = g_Q[p * 64 + lane + 32];
    const float* Sb = g_S + b * HWP * 64;
    const float* Rb = g_R + b * HWP * 64;

    float sc[16];
    int   bs[16];
#pragma unroll
    for (int k = 0; k < 16; k++) {
        int fk = __shfl_sync(0xffffffffu, fl, k);
        int base = fk * 64;
        bs[k] = base;
        float part = q0 * Sb[base + lane] + q1 * Sb[base + lane + 32];
#pragma unroll
        for (int o = 16; o; o >>= 1) part += __shfl_xor_sync(0xffffffffu, part, o);
        sc[k] = part;
    }

    float mx = sc[0];
#pragma unroll
    for (int k = 1; k < 16; k++) mx = fmaxf(mx, sc[k]);
    float sum = 0.f;
#pragma unroll
    for (int k = 0; k < 16; k++) { sc[k] = __expf(sc[k] - mx); sum += sc[k]; }
    const float inv = 1.f / sum;

    float acc0 = 0.f, acc1 = 0.f, mv = 0.f;
#pragma unroll
    for (int k = 0; k < 16; k++) {
        float m = sc[k] * inv;
        acc0 += m * Rb[bs[k] + lane];
        acc1 += m * Rb[bs[k] + lane + 32];
        if (lane == k) mv = m;
    }

    g_battn[p * 64 + lane]      = acc0;
    g_battn[p * 64 + lane + 32] = acc1;
    if (lane < 16) Mout[p * 16 + lane] = mv;
}

// ---------------- fusion 1x1: concat(buf_attn, x_left) -> out (NCHW) --------
__global__ void __launch_bounds__(256) fuse_k(const float* __restrict__ xl,
                                              const float* __restrict__ fw,
                                              const float* __restrict__ fb,
                                              float* __restrict__ out) {
    __shared__ float wsm[128 * 64];       // 32 KB  [cin*64 + co]
    __shared__ __align__(16) float vsm[8 * 258];  // 8.25 KB chunked transpose

    const int t  = threadIdx.x;
    const int b  = blockIdx.y;
    const int p0 = blockIdx.x * 256;

    for (int j = t; j < 8192; j += 256) {
        int cin = j >> 6, co = j & 63;
        wsm[j] = fw[co * 128 + cin];
    }

    const float* ba  = g_battn + b * HWP * 64;
    const float* xlb = xl + b * 64 * HWP;
    const int cg = t >> 6, q = t & 63;
    unsigned long long acc[16][2];
#pragma unroll
    for (int c = 0; c < 16; c++) { acc[c][0] = 0ull; acc[c][1] = 0ull; }
    __syncthreads();

    // first 64 cins: pixel-major buf_attn, staged through smem in chunks of 8
    for (int cc0 = 0; cc0 < 64; cc0 += 8) {
        __syncthreads();
        for (int i = t; i < 2048; i += 256) {
            int c = i & 7, px = i >> 3;
            vsm[c * 258 + px] = ba[(p0 + px) * 64 + cc0 + c];
        }
        __syncthreads();
#pragma unroll
        for (int cl = 0; cl < 8; cl++) {
            const int cin = cc0 + cl;
            unsigned long long v0 = *(const unsigned long long*)&vsm[cl * 258 + 2 * q];
            unsigned long long v1 = *(const unsigned long long*)&vsm[cl * 258 + 128 + 2 * q];
            const int wb = cin * 64 + cg * 16;
#pragma unroll
            for (int c = 0; c < 16; c++) {
                float wv = wsm[wb + c];
                unsigned long long w2 = pk2(wv, wv);
                acc[c][0] = fma2(w2, v0, acc[c][0]);
                acc[c][1] = fma2(w2, v1, acc[c][1]);
            }
        }
    }
    // cins 64..127: channel-major x_left, direct coalesced loads
#pragma unroll 4
    for (int cin = 64; cin < 128; cin++) {
        unsigned long long v0 =
            *(const unsigned long long*)(xlb + (cin - 64) * HWP + p0 + 2 * q);
        unsigned long long v1 =
            *(const unsigned long long*)(xlb + (cin - 64) * HWP + p0 + 128 + 2 * q);
        const int wb = cin * 64 + cg * 16;
#pragma unroll
        for (int c = 0; c < 16; c++) {
            float wv = wsm[wb + c];
            unsigned long long w2 = pk2(wv, wv);
            acc[c][0] = fma2(w2, v0, acc[c][0]);
            acc[c][1] = fma2(w2, v1, acc[c][1]);
        }
    }

#pragma unroll
    for (int c = 0; c < 16; c++) {
        const int co = cg * 16 + c;
        const float bb = fb[co];
#pragma unroll
        for (int r = 0; r < 2; r++) {
            float lo, hi;
            upk2(acc[c][r], lo, hi);
            float2 o; o.x = lo + bb; o.y = hi + bb;
            *(float2*)(out + (b * 64 + co) * HWP + p0 + 128 * r + 2 * q) = o;
        }
    }
}

// ---------------- launch ----------------------------------------------------
extern "C" void kernel_launch(void* const* d_in, const int* in_sizes, int n_in,
                              void* d_out, int out_size) {
    const float* xl  = (const float*)d_in[0];
    const float* xr  = (const float*)d_in[1];
    const int*   xxs = (const int*)d_in[2];
    const int*   yys = (const int*)d_in[3];
    // is_training may or may not be materialized as an input; detect by size.
    const int wbase = (in_sizes[4] == 1) ? 5 : 4;
    const float* rb_w1 = (const float*)d_in[wbase + 0];
    const float* rb_w2 = (const float*)d_in[wbase + 1];
    const float* b1w   = (const float*)d_in[wbase + 2];
    const float* b1b   = (const float*)d_in[wbase + 3];
    const float* b2w   = (const float*)d_in[wbase + 4];
    const float* b2b   = (const float*)d_in[wbase + 5];
    const float* b3w   = (const float*)d_in[wbase + 6];
    const float* b3b   = (const float*)d_in[wbase + 7];
    const float* fw    = (const float*)d_in[wbase + 8];
    const float* fb    = (const float*)d_in[wbase + 9];

    float* out  = (float*)d_out;
    float* Mout = out + BB * CC * HWP;  // (B, HW, 1, K) after out (B,C,H,W)

    dim3 g3(WW / 32, HH / 8, 4);
    conv3x3_k<0><<<g3, 256>>>(xl, xr, rb_w1);
    conv3x3_k<1><<<g3, 256>>>(xl, xr, rb_w2);

    dim3 g1(HWP / 256, BB);
    conv1x1_k<<<g1, 256>>>(b1w, b1b, 0);
    conv1x1_k<<<g1, 256>>>(b2w, b2b, 1);
    conv1x1_k<<<g1, 256>>>(b3w, b3b, 2);

    attn_k<<<BB * HWP / 8, 256>>>(xxs, yys, Mout);

    fuse_k<<<g1, 256>>>(xl, fw, fb, out);
}

// round 2
// speedup vs baseline: 1.3281x; 1.3281x over previous
#include <cuda_runtime.h>

#define HH 128
#define WW 256
#define HWP 32768
#define CC 64
#define BB 2
#define KK 16

typedef unsigned long long u64;

// ---------------- scratch ----------------------------------------------------
__device__ float g_tmp[4 * CC * HWP];
__device__ float g_buf[4 * CC * HWP];
__device__ float g_Q[BB * HWP * CC];
__device__ float g_S[BB * HWP * CC];
__device__ float g_R[BB * HWP * CC];
__device__ float g_battn[BB * HWP * CC];

// ---------------- packed f32x2 helpers ---------------------------------------
__device__ __forceinline__ u64 pk2(float lo, float hi) {
    u64 r;
    asm("mov.b64 %0, {%1, %2};" : "=l"(r) : "f"(lo), "f"(hi));
    return r;
}
__device__ __forceinline__ void upk2(u64 v, float& lo, float& hi) {
    asm("mov.b64 {%0, %1}, %2;" : "=f"(lo), "=f"(hi) : "l"(v));
}
__device__ __forceinline__ u64 fma2(u64 a, u64 b, u64 c) {
    u64 d;
    asm("fma.rn.f32x2 %0, %1, %2, %3;" : "=l"(d) : "l"(a), "l"(b), "l"(c));
    return d;
}

// ---------------- conv 3x3 (pad=1), 64->64, redesigned ------------------------
// Block: 256 thr. Out tile: 32(x) x 4(y), 32 couts (cohalf). 2 blocks/SM.
// Smem: full weights for the 32-cout half, cout-pair packed [cin][tap][cp16]
//       (73728 B) + input chunk of 16 cins with halo [16][6][34] (13056 B).
// Thread: cg=t>>6 -> 4 copairs (8 couts); pg=t&63: ox=pg&31, ygrp=pg>>5 -> 2 rows.
#define CONV_SMEM (73728 + 13056)

template <int MODE>
__global__ void __launch_bounds__(256, 2) conv3x3_k(const float* __restrict__ xl,
                                                    const float* __restrict__ xr,
                                                    const float* __restrict__ w) {
    extern __shared__ unsigned char dynsm[];
    u64* wsm = (u64*)dynsm;                    // [cin*9+tap]*16 + cp  (9216)
    float* tile = (float*)(dynsm + 73728);     // [c][r][x] = c*204 + r*34 + x

    const int t = threadIdx.x;
    const int img = blockIdx.z >> 1;
    const int cohalf = blockIdx.z & 1;
    const int gx0 = blockIdx.x * 32;
    const int gy0 = blockIdx.y * 4;

    const float* in;
    if (MODE == 0)
        in = (img < 2) ? (xl + img * CC * HWP) : (xr + (img - 2) * CC * HWP);
    else
        in = g_tmp + img * CC * HWP;

    // weight fill: 9216 u64, cout-pair packed
    for (int j = t; j < 9216; j += 256) {
        int cp = j & 15;
        int rest = j >> 4;           // cin*9 + tap
        int cin = rest / 9;
        int tap = rest - cin * 9;
        int co = cohalf * 32 + 2 * cp;
        float w0 = w[(co * 64 + cin) * 9 + tap];
        float w1 = w[((co + 1) * 64 + cin) * 9 + tap];
        wsm[j] = pk2(w0, w1);
    }

    const int cg = t >> 6;
    const int pg = t & 63;
    const int ox = pg & 31;
    const int ygrp = pg >> 5;
    const int r0 = ygrp * 2;

    u64 acc[2][4];
#pragma unroll
    for (int rr = 0; rr < 2; rr++)
#pragma unroll
        for (int cp = 0; cp < 4; cp++) acc[rr][cp] = 0ull;

    for (int cc0 = 0; cc0 < 64; cc0 += 16) {
        __syncthreads();
        // load 16-cin input chunk with halo (rows gy0-1 .. gy0+4)
        for (int i = t; i < 3264; i += 256) {
            int c = i / 204;
            int rem = i - c * 204;
            int r = rem / 34;
            int x = rem - r * 34;
            int gy = gy0 - 1 + r, gx = gx0 - 1 + x;
            float v = 0.f;
            if ((unsigned)gy < HH && (unsigned)gx < WW)
                v = in[(cc0 + c) * HWP + gy * WW + gx];
            tile[i] = v;
        }
        __syncthreads();

#pragma unroll 2
        for (int c = 0; c < 16; c++) {
            const float* tb = tile + c * 204 + r0 * 34 + ox;
            u64 dv[4][3];
#pragma unroll
            for (int r = 0; r < 4; r++)
#pragma unroll
                for (int dx = 0; dx < 3; dx++) {
                    float v = tb[r * 34 + dx];
                    dv[r][dx] = pk2(v, v);
                }
            const u64* wb = wsm + ((cc0 + c) * 9) * 16 + cg * 4;
#pragma unroll
            for (int dy = 0; dy < 3; dy++)
#pragma unroll
                for (int dx = 0; dx < 3; dx++) {
                    const u64* wt = wb + (dy * 3 + dx) * 16;
#pragma unroll
                    for (int cp = 0; cp < 4; cp++) {
                        u64 w2 = wt[cp];
                        acc[0][cp] = fma2(w2, dv[dy][dx], acc[0][cp]);
                        acc[1][cp] = fma2(w2, dv[dy + 1][dx], acc[1][cp]);
                    }
                }
        }
    }

    float* out = ((MODE == 0) ? g_tmp : g_buf) + img * CC * HWP;
    const float* res = nullptr;
    if (MODE == 1)
        res = (img < 2) ? (xl + img * CC * HWP) : (xr + (img - 2) * CC * HWP);

    const int cobase = cohalf * 32 + cg * 8;
#pragma unroll
    for (int rr = 0; rr < 2; rr++) {
        const int gy = gy0 + r0 + rr;
#pragma unroll
        for (int cp = 0; cp < 4; cp++) {
            float lo, hi;
            upk2(acc[rr][cp], lo, hi);
            int co = cobase + 2 * cp;
            int off0 = co * HWP + gy * WW + gx0 + ox;
            int off1 = off0 + HWP;
            if (MODE == 0) {
                lo = lo > 0.f ? lo : 0.1f * lo;
                hi = hi > 0.f ? hi : 0.1f * hi;
            } else {
                lo += res[off0];
                hi += res[off1];
            }
            out[off0] = lo;
            out[off1] = hi;
        }
    }
}

// ---------------- fused 1x1 convs: Q (left) / S+R (right) ---------------------
// MODE 0: Q only. MODE 1: S and R, sharing input loads.
// Block: 256 thr, 128 pixels. cg=t>>6 -> 16 couts; q=t&63 -> pixel pair 2q.
#define QSR_SMEM 66560

template <int MODE>
__global__ void __launch_bounds__(256) qsr_k(const float* __restrict__ wA,
                                             const float* __restrict__ bA,
                                             const float* __restrict__ wB,
                                             const float* __restrict__ bB) {
    extern __shared__ unsigned char dynsm[];
    u64* wsmA = (u64*)dynsm;            // [cin*64 + co], dup-packed
    u64* wsmB = wsmA + 4096;
    float* st = (float*)dynsm;          // staging reuses pool (128 x 65)

    const int t = threadIdx.x;
    const int b = blockIdx.y;
    const int p0 = blockIdx.x * 128;
    const float* in = g_buf + ((MODE == 0) ? b : (2 + b)) * CC * HWP;

    for (int j = t; j < 4096; j += 256) {
        int cin = j >> 6, co = j & 63;
        float v = wA[co * 64 + cin];
        wsmA[j] = pk2(v, v);
        if (MODE == 1) {
            float v2 = wB[co * 64 + cin];
            wsmB[j] = pk2(v2, v2);
        }
    }
    __syncthreads();

    const int cg = t >> 6, q = t & 63;
    u64 accA[16], accB[16];
#pragma unroll
    for (int c = 0; c < 16; c++) { accA[c] = 0ull; accB[c] = 0ull; }

#pragma unroll 4
    for (int cin = 0; cin < 64; cin++) {
        u64 v = *(const u64*)(in + cin * HWP + p0 + 2 * q);
        const int wb = cin * 64 + cg * 16;
#pragma unroll
        for (int c = 0; c < 16; c++) {
            accA[c] = fma2(wsmA[wb + c], v, accA[c]);
            if (MODE == 1) accB[c] = fma2(wsmB[wb + c], v, accB[c]);
        }
    }

    float* outA = ((MODE == 0) ? g_Q : g_S) + b * HWP * CC;
    // stage + coalesced pixel-major write, mat A
    __syncthreads();
#pragma unroll
    for (int c = 0; c < 16; c++) {
        float lo, hi;
        upk2(accA[c], lo, hi);
        st[(2 * q) * 65 + cg * 16 + c] = lo;
        st[(2 * q + 1) * 65 + cg * 16 + c] = hi;
    }
    __syncthreads();
    for (int i = t; i < 8192; i += 256) {
        int px = i >> 6, co = i & 63;
        outA[(p0 + px) * 64 + co] = st[px * 65 + co] + bA[co];
    }
    if (MODE == 1) {
        float* outB = g_R + b * HWP * CC;
        __syncthreads();
#pragma unroll
        for (int c = 0; c < 16; c++) {
            float lo, hi;
            upk2(accB[c], lo, hi);
            st[(2 * q) * 65 + cg * 16 + c] = lo;
            st[(2 * q + 1) * 65 + cg * 16 + c] = hi;
        }
        __syncthreads();
        for (int i = t; i < 8192; i += 256) {
            int px = i >> 6, co = i & 63;
            outB[(p0 + px) * 64 + co] = st[px * 65 + co] + bB[co];
        }
    }
}

// ---------------- attention: warp per pixel ----------------------------------
__global__ void __launch_bounds__(256) attn_k(const int* __restrict__ xxs,
                                              const int* __restrict__ yys,
                                              float* __restrict__ Mout) {
    const int t = threadIdx.x;
    const int lane = t & 31;
    const int p = blockIdx.x * 8 + (t >> 5);
    const int b = p >> 15;

    int fl = 0;
    if (lane < 16) fl = xxs[p * 16 + lane] * WW + yys[p * 16 + lane];

    const float q0 = g_Q[p * 64 + lane];
    const float q1 = g_Q[p * 64 + lane + 32];
    const float* Sb = g_S + b * HWP * 64;
    const float* Rb = g_R + b * HWP * 64;

    float sc[16];
    int bs[16];
#pragma unroll
    for (int k = 0; k < 16; k++) {
        int fk = __shfl_sync(0xffffffffu, fl, k);
        int base = fk * 64;
        bs[k] = base;
        float part = q0 * Sb[base + lane] + q1 * Sb[base + lane + 32];
#pragma unroll
        for (int o = 16; o; o >>= 1) part += __shfl_xor_sync(0xffffffffu, part, o);
        sc[k] = part;
    }

    float mx = sc[0];
#pragma unroll
    for (int k = 1; k < 16; k++) mx = fmaxf(mx, sc[k]);
    float sum = 0.f;
#pragma unroll
    for (int k = 0; k < 16; k++) { sc[k] = __expf(sc[k] - mx); sum += sc[k]; }
    const float inv = 1.f / sum;

    float acc0 = 0.f, acc1 = 0.f, mv = 0.f;
#pragma unroll
    for (int k = 0; k < 16; k++) {
        float m = sc[k] * inv;
        acc0 += m * Rb[bs[k] + lane];
        acc1 += m * Rb[bs[k] + lane + 32];
        if (lane == k) mv = m;
    }

    g_battn[p * 64 + lane] = acc0;
    g_battn[p * 64 + lane + 32] = acc1;
    if (lane < 16) Mout[p * 16 + lane] = mv;
}

// ---------------- fusion 1x1: concat(buf_attn, x_left) -> out -----------------
__global__ void __launch_bounds__(256) fuse_k(const float* __restrict__ xl,
                                              const float* __restrict__ fw,
                                              const float* __restrict__ fb,
                                              float* __restrict__ out) {
    __shared__ float wsm[128 * 64];
    __shared__ __align__(16) float vsm[8 * 258];

    const int t = threadIdx.x;
    const int b = blockIdx.y;
    const int p0 = blockIdx.x * 256;

    for (int j = t; j < 8192; j += 256) {
        int cin = j >> 6, co = j & 63;
        wsm[j] = fw[co * 128 + cin];
    }

    const float* ba = g_battn + b * HWP * 64;
    const float* xlb = xl + b * 64 * HWP;
    const int cg = t >> 6, q = t & 63;
    u64 acc[16][2];
#pragma unroll
    for (int c = 0; c < 16; c++) { acc[c][0] = 0ull; acc[c][1] = 0ull; }
    __syncthreads();

    for (int cc0 = 0; cc0 < 64; cc0 += 8) {
        __syncthreads();
        for (int i = t; i < 2048; i += 256) {
            int c = i & 7, px = i >> 3;
            vsm[c * 258 + px] = ba[(p0 + px) * 64 + cc0 + c];
        }
        __syncthreads();
#pragma unroll
        for (int cl = 0; cl < 8; cl++) {
            const int cin = cc0 + cl;
            u64 v0 = *(const u64*)&vsm[cl * 258 + 2 * q];
            u64 v1 = *(const u64*)&vsm[cl * 258 + 128 + 2 * q];
            const int wb = cin * 64 + cg * 16;
#pragma unroll
            for (int c = 0; c < 16; c++) {
                float wv = wsm[wb + c];
                u64 w2 = pk2(wv, wv);
                acc[c][0] = fma2(w2, v0, acc[c][0]);
                acc[c][1] = fma2(w2, v1, acc[c][1]);
            }
        }
    }
#pragma unroll 8
    for (int cin = 64; cin < 128; cin++) {
        u64 v0 = *(const u64*)(xlb + (cin - 64) * HWP + p0 + 2 * q);
        u64 v1 = *(const u64*)(xlb + (cin - 64) * HWP + p0 + 128 + 2 * q);
        const int wb = cin * 64 + cg * 16;
#pragma unroll
        for (int c = 0; c < 16; c++) {
            float wv = wsm[wb + c];
            u64 w2 = pk2(wv, wv);
            acc[c][0] = fma2(w2, v0, acc[c][0]);
            acc[c][1] = fma2(w2, v1, acc[c][1]);
        }
    }

#pragma unroll
    for (int c = 0; c < 16; c++) {
        const int co = cg * 16 + c;
        const float bb = fb[co];
#pragma unroll
        for (int r = 0; r < 2; r++) {
            float lo, hi;
            upk2(acc[c][r], lo, hi);
            float2 o;
            o.x = lo + bb;
            o.y = hi + bb;
            *(float2*)(out + (b * 64 + co) * HWP + p0 + 128 * r + 2 * q) = o;
        }
    }
}

// ---------------- launch ------------------------------------------------------
extern "C" void kernel_launch(void* const* d_in, const int* in_sizes, int n_in,
                              void* d_out, int out_size) {
    const float* xl = (const float*)d_in[0];
    const float* xr = (const float*)d_in[1];
    const int* xxs = (const int*)d_in[2];
    const int* yys = (const int*)d_in[3];
    const int wbase = (in_sizes[4] == 1) ? 5 : 4;
    const float* rb_w1 = (const float*)d_in[wbase + 0];
    const float* rb_w2 = (const float*)d_in[wbase + 1];
    const float* b1w = (const float*)d_in[wbase + 2];
    const float* b1b = (const float*)d_in[wbase + 3];
    const float* b2w = (const float*)d_in[wbase + 4];
    const float* b2b = (const float*)d_in[wbase + 5];
    const float* b3w = (const float*)d_in[wbase + 6];
    const float* b3b = (const float*)d_in[wbase + 7];
    const float* fw = (const float*)d_in[wbase + 8];
    const float* fb = (const float*)d_in[wbase + 9];

    float* out = (float*)d_out;
    float* Mout = out + BB * CC * HWP;

    // host-side attr calls (not stream ops; fine under graph capture)
    cudaFuncSetAttribute(conv3x3_k<0>, cudaFuncAttributeMaxDynamicSharedMemorySize, CONV_SMEM);
    cudaFuncSetAttribute(conv3x3_k<1>, cudaFuncAttributeMaxDynamicSharedMemorySize, CONV_SMEM);
    cudaFuncSetAttribute(qsr_k<0>, cudaFuncAttributeMaxDynamicSharedMemorySize, QSR_SMEM);
    cudaFuncSetAttribute(qsr_k<1>, cudaFuncAttributeMaxDynamicSharedMemorySize, QSR_SMEM);

    dim3 g3(WW / 32, HH / 4, 8);
    conv3x3_k<0><<<g3, 256, CONV_SMEM>>>(xl, xr, rb_w1);
    conv3x3_k<1><<<g3, 256, CONV_SMEM>>>(xl, xr, rb_w2);

    dim3 gq(HWP / 128, BB);
    qsr_k<0><<<gq, 256, QSR_SMEM>>>(b1w, b1b, b1w, b1b);
    qsr_k<1><<<gq, 256, QSR_SMEM>>>(b2w, b2b, b3w, b3b);

    attn_k<<<BB * HWP / 8, 256>>>(xxs, yys, Mout);

    fuse_k<<<dim3(HWP / 256, BB), 256>>>(xl, fw, fb, out);
}

// round 3
// speedup vs baseline: 1.8243x; 1.3736x over previous
#include <cuda_runtime.h>

#define HH 128
#define WW 256
#define HWP 32768
#define CC 64
#define BB 2
#define KK 16

typedef unsigned long long u64;

// ---------------- scratch ----------------------------------------------------
__device__ float g_tmp[4 * CC * HWP];
__device__ float g_buf[4 * CC * HWP];
__device__ float g_Q[BB * HWP * CC];
__device__ float g_S[BB * HWP * CC];
__device__ float g_R[BB * HWP * CC];
__device__ float g_battn[BB * HWP * CC];
// packed weights: conv [conv][cohalf][cin*9+tap][cp16] pair-packed
__device__ u64 g_wc[2][2][576 * 16];
// qsr dup-packed [mat][cin*64+co]
__device__ u64 g_wq[3][4096];

// ---------------- packed f32x2 helpers ---------------------------------------
__device__ __forceinline__ u64 pk2(float lo, float hi) {
    u64 r;
    asm("mov.b64 %0, {%1, %2};" : "=l"(r) : "f"(lo), "f"(hi));
    return r;
}
__device__ __forceinline__ void upk2(u64 v, float& lo, float& hi) {
    asm("mov.b64 {%0, %1}, %2;" : "=f"(lo), "=f"(hi) : "l"(v));
}
__device__ __forceinline__ u64 fma2(u64 a, u64 b, u64 c) {
    u64 d;
    asm("fma.rn.f32x2 %0, %1, %2, %3;" : "=l"(d) : "l"(a), "l"(b), "l"(c));
    return d;
}

// ---------------- prep: pack weights into device globals ----------------------
__global__ void __launch_bounds__(256) prep_k(const float* __restrict__ w1,
                                              const float* __restrict__ w2,
                                              const float* __restrict__ qw,
                                              const float* __restrict__ sw,
                                              const float* __restrict__ rw) {
    int i = blockIdx.x * 256 + threadIdx.x;  // 0..49151
    if (i < 36864) {
        int conv = i / 18432;
        int r = i % 18432;
        int h = r / 9216;
        int j = r % 9216;
        int cpl = j & 15;
        int ct = j >> 4;  // cin*9+tap
        int cin = ct / 9, tap = ct - cin * 9;
        int co = h * 32 + 2 * cpl;
        const float* w = conv ? w2 : w1;
        g_wc[conv][h][j] = pk2(w[(co * 64 + cin) * 9 + tap], w[((co + 1) * 64 + cin) * 9 + tap]);
    } else if (i < 49152) {
        int j = i - 36864;
        int mat = j >> 12;
        int e = j & 4095;
        int cin = e >> 6, co = e & 63;
        const float* w = (mat == 0) ? qw : (mat == 1) ? sw : rw;
        float v = w[co * 64 + cin];
        g_wq[mat][e] = pk2(v, v);
    }
}

// ---------------- conv 3x3 (pad=1), 64->64 ------------------------------------
// Block 256 thr, 2/SM. Tile: 32x x 8y x 32 couts (cohalf).
// Thread: cg=t>>6 -> 4 cout-pairs (8 couts); pg=t&63: ox=pg&31, yg=pg>>5 -> 4 rows.
// Smem: packed weights 9216 u64 (73728 B) + 8-cin input chunk (2720 f, 10880 B).
#define CONV_SMEM (73728 + 10880)

template <int MODE>
__global__ void __launch_bounds__(256, 2) conv3x3_k(const float* __restrict__ xl,
                                                    const float* __restrict__ xr) {
    extern __shared__ unsigned char dynsm[];
    u64* wsm = (u64*)dynsm;                 // [(cin*9+tap)*16 + cpl]
    float* tile = (float*)(dynsm + 73728);  // [c*340 + r*34 + x]

    const int t = threadIdx.x;
    const int img = blockIdx.z >> 1;
    const int h = blockIdx.z & 1;
    const int gx0 = blockIdx.x * 32;
    const int gy0 = blockIdx.y * 8;

    const float* in;
    if (MODE == 0)
        in = (img < 2) ? (xl + img * CC * HWP) : (xr + (img - 2) * CC * HWP);
    else
        in = g_tmp + img * CC * HWP;

    // coalesced packed-weight fill
    {
        const u64* ws = g_wc[MODE][h];
        for (int j = t; j < 9216; j += 256) wsm[j] = ws[j];
    }

    const int cg = t >> 6;
    const int pg = t & 63;
    const int ox = pg & 31;
    const int ry = (pg >> 5) * 4;  // first output row in tile

    u64 acc[4][4];
#pragma unroll
    for (int rr = 0; rr < 4; rr++)
#pragma unroll
        for (int cp = 0; cp < 4; cp++) acc[rr][cp] = 0ull;

    for (int cc0 = 0; cc0 < 64; cc0 += 8) {
        __syncthreads();
        for (int i = t; i < 2720; i += 256) {
            int c = i / 340;
            int rem = i - c * 340;
            int r = rem / 34;
            int x = rem - r * 34;
            int gy = gy0 - 1 + r, gx = gx0 - 1 + x;
            float v = 0.f;
            if ((unsigned)gy < HH && (unsigned)gx < WW)
                v = in[(cc0 + c) * HWP + gy * WW + gx];
            tile[i] = v;
        }
        __syncthreads();

#pragma unroll 2
        for (int c = 0; c < 8; c++) {
            const float* tb = tile + c * 340 + ry * 34 + ox;
            u64 dv[6][3];
#pragma unroll
            for (int r = 0; r < 6; r++)
#pragma unroll
                for (int dx = 0; dx < 3; dx++) {
                    float v = tb[r * 34 + dx];
                    dv[r][dx] = pk2(v, v);
                }
            const u64* wb = wsm + (cc0 + c) * 144 + cg * 4;
#pragma unroll
            for (int dy = 0; dy < 3; dy++)
#pragma unroll
                for (int dx = 0; dx < 3; dx++) {
                    const u64* wt = wb + (dy * 3 + dx) * 16;
#pragma unroll
                    for (int cp = 0; cp < 4; cp++) {
                        u64 w2 = wt[cp];
#pragma unroll
                        for (int rr = 0; rr < 4; rr++)
                            acc[rr][cp] = fma2(w2, dv[rr + dy][dx], acc[rr][cp]);
                    }
                }
        }
    }

    float* out = ((MODE == 0) ? g_tmp : g_buf) + img * CC * HWP;
    const float* res = nullptr;
    if (MODE == 1)
        res = (img < 2) ? (xl + img * CC * HWP) : (xr + (img - 2) * CC * HWP);

#pragma unroll
    for (int rr = 0; rr < 4; rr++) {
        const int gy = gy0 + ry + rr;
#pragma unroll
        for (int cp = 0; cp < 4; cp++) {
            float lo, hi;
            upk2(acc[rr][cp], lo, hi);
            int co = h * 32 + cg * 8 + 2 * cp;
            int off0 = co * HWP + gy * WW + gx0 + ox;
            int off1 = off0 + HWP;
            if (MODE == 0) {
                lo = lo > 0.f ? lo : 0.1f * lo;
                hi = hi > 0.f ? hi : 0.1f * hi;
            } else {
                lo += res[off0];
                hi += res[off1];
            }
            out[off0] = lo;
            out[off1] = hi;
        }
    }
}

// ---------------- Q/S/R 1x1 convs: register-tiled GEMM ------------------------
// grid (256 px-blocks, 3 mats). Thread: 8 couts x 8 pixels.
#define QSR_SMEM (32768 + 16640)

__global__ void __launch_bounds__(256, 2) qsr_k(const float* __restrict__ b1b,
                                                const float* __restrict__ b2b,
                                                const float* __restrict__ b3b) {
    extern __shared__ unsigned char dynsm[];
    u64* wsm = (u64*)dynsm;                // 4096 dup-packed
    float* st = (float*)(dynsm + 32768);   // 64 px x 65

    const int t = threadIdx.x;
    const int mat = blockIdx.y;
    const int p0 = blockIdx.x * 256;       // global pixel base (b folded)
    const int b = p0 >> 15;
    const int lp = p0 & 32767;

    const float* in = g_buf + (((mat == 0) ? 0 : 2) + b) * CC * HWP + lp;
    float* outp = ((mat == 0) ? g_Q : (mat == 1) ? g_S : g_R) + p0 * 64;
    const float* bias = (mat == 0) ? b1b : (mat == 1) ? b2b : b3b;

    {
        const u64* ws = g_wq[mat];
        for (int j = t; j < 4096; j += 256) wsm[j] = ws[j];
    }
    __syncthreads();

    const int cg = t >> 5;   // cout group: couts cg*8 .. cg*8+7
    const int tx = t & 31;   // pixel pair 2*tx + 64*j

    u64 acc[8][4];
#pragma unroll
    for (int co = 0; co < 8; co++)
#pragma unroll
        for (int j = 0; j < 4; j++) acc[co][j] = 0ull;

#pragma unroll 2
    for (int cin = 0; cin < 64; cin++) {
        u64 v[4];
#pragma unroll
        for (int j = 0; j < 4; j++)
            v[j] = *(const u64*)(in + cin * HWP + 2 * tx + 64 * j);
        const u64* wb = wsm + cin * 64 + cg * 8;
#pragma unroll
        for (int co = 0; co < 8; co++) {
            u64 w2 = wb[co];
#pragma unroll
            for (int j = 0; j < 4; j++) acc[co][j] = fma2(w2, v[j], acc[co][j]);
        }
    }

    // transpose-stage 64-pixel chunks, coalesced pixel-major writes
#pragma unroll
    for (int j = 0; j < 4; j++) {
        __syncthreads();
#pragma unroll
        for (int co = 0; co < 8; co++) {
            float lo, hi;
            upk2(acc[co][j], lo, hi);
            st[(2 * tx) * 65 + cg * 8 + co] = lo;
            st[(2 * tx + 1) * 65 + cg * 8 + co] = hi;
        }
        __syncthreads();
        for (int i = t; i < 4096; i += 256) {
            int px = i >> 6, c = i & 63;
            outp[(64 * j + px) * 64 + c] = st[px * 65 + c] + bias[c];
        }
    }
}

// ---------------- attention: warp per pixel ----------------------------------
__global__ void __launch_bounds__(256) attn_k(const int* __restrict__ xxs,
                                              const int* __restrict__ yys,
                                              float* __restrict__ Mout) {
    const int t = threadIdx.x;
    const int lane = t & 31;
    const int p = blockIdx.x * 8 + (t >> 5);
    const int b = p >> 15;

    int fl = 0;
    if (lane < 16) fl = xxs[p * 16 + lane] * WW + yys[p * 16 + lane];

    const float q0 = g_Q[p * 64 + lane];
    const float q1 = g_Q[p * 64 + lane + 32];
    const float* Sb = g_S + b * HWP * 64;
    const float* Rb = g_R + b * HWP * 64;

    float sc[16];
    int bs[16];
#pragma unroll
    for (int k = 0; k < 16; k++) {
        int fk = __shfl_sync(0xffffffffu, fl, k);
        int base = fk * 64;
        bs[k] = base;
        float part = q0 * Sb[base + lane] + q1 * Sb[base + lane + 32];
#pragma unroll
        for (int o = 16; o; o >>= 1) part += __shfl_xor_sync(0xffffffffu, part, o);
        sc[k] = part;
    }

    float mx = sc[0];
#pragma unroll
    for (int k = 1; k < 16; k++) mx = fmaxf(mx, sc[k]);
    float sum = 0.f;
#pragma unroll
    for (int k = 0; k < 16; k++) { sc[k] = __expf(sc[k] - mx); sum += sc[k]; }
    const float inv = 1.f / sum;

    float acc0 = 0.f, acc1 = 0.f, mv = 0.f;
#pragma unroll
    for (int k = 0; k < 16; k++) {
        float m = sc[k] * inv;
        acc0 += m * Rb[bs[k] + lane];
        acc1 += m * Rb[bs[k] + lane + 32];
        if (lane == k) mv = m;
    }

    g_battn[p * 64 + lane] = acc0;
    g_battn[p * 64 + lane + 32] = acc1;
    if (lane < 16) Mout[p * 16 + lane] = mv;
}

// ---------------- fusion 1x1: concat(buf_attn, x_left) -> out -----------------
__global__ void __launch_bounds__(256) fuse_k(const float* __restrict__ xl,
                                              const float* __restrict__ fw,
                                              const float* __restrict__ fb,
                                              float* __restrict__ out) {
    __shared__ float wsm[128 * 64];
    __shared__ __align__(16) float vsm[8 * 258];

    const int t = threadIdx.x;
    const int b = blockIdx.y;
    const int p0 = blockIdx.x * 256;

    for (int j = t; j < 8192; j += 256) {
        int cin = j >> 6, co = j & 63;
        wsm[j] = fw[co * 128 + cin];
    }

    const float* ba = g_battn + b * HWP * 64;
    const float* xlb = xl + b * 64 * HWP;
    const int cg = t >> 6, q = t & 63;
    u64 acc[16][2];
#pragma unroll
    for (int c = 0; c < 16; c++) { acc[c][0] = 0ull; acc[c][1] = 0ull; }
    __syncthreads();

    for (int cc0 = 0; cc0 < 64; cc0 += 8) {
        __syncthreads();
        for (int i = t; i < 2048; i += 256) {
            int c = i & 7, px = i >> 3;
            vsm[c * 258 + px] = ba[(p0 + px) * 64 + cc0 + c];
        }
        __syncthreads();
#pragma unroll
        for (int cl = 0; cl < 8; cl++) {
            const int cin = cc0 + cl;
            u64 v0 = *(const u64*)&vsm[cl * 258 + 2 * q];
            u64 v1 = *(const u64*)&vsm[cl * 258 + 128 + 2 * q];
            const int wb = cin * 64 + cg * 16;
#pragma unroll
            for (int c = 0; c < 16; c++) {
                float wv = wsm[wb + c];
                u64 w2 = pk2(wv, wv);
                acc[c][0] = fma2(w2, v0, acc[c][0]);
                acc[c][1] = fma2(w2, v1, acc[c][1]);
            }
        }
    }
#pragma unroll 8
    for (int cin = 64; cin < 128; cin++) {
        u64 v0 = *(const u64*)(xlb + (cin - 64) * HWP + p0 + 2 * q);
        u64 v1 = *(const u64*)(xlb + (cin - 64) * HWP + p0 + 128 + 2 * q);
        const int wb = cin * 64 + cg * 16;
#pragma unroll
        for (int c = 0; c < 16; c++) {
            float wv = wsm[wb + c];
            u64 w2 = pk2(wv, wv);
            acc[c][0] = fma2(w2, v0, acc[c][0]);
            acc[c][1] = fma2(w2, v1, acc[c][1]);
        }
    }

#pragma unroll
    for (int c = 0; c < 16; c++) {
        const int co = cg * 16 + c;
        const float bb = fb[co];
#pragma unroll
        for (int r = 0; r < 2; r++) {
            float lo, hi;
            upk2(acc[c][r], lo, hi);
            float2 o;
            o.x = lo + bb;
            o.y = hi + bb;
            *(float2*)(out + (b * 64 + co) * HWP + p0 + 128 * r + 2 * q) = o;
        }
    }
}

// ---------------- launch ------------------------------------------------------
extern "C" void kernel_launch(void* const* d_in, const int* in_sizes, int n_in,
                              void* d_out, int out_size) {
    const float* xl = (const float*)d_in[0];
    const float* xr = (const float*)d_in[1];
    const int* xxs = (const int*)d_in[2];
    const int* yys = (const int*)d_in[3];
    const int wbase = (in_sizes[4] == 1) ? 5 : 4;
    const float* rb_w1 = (const float*)d_in[wbase + 0];
    const float* rb_w2 = (const float*)d_in[wbase + 1];
    const float* b1w = (const float*)d_in[wbase + 2];
    const float* b1b = (const float*)d_in[wbase + 3];
    const float* b2w = (const float*)d_in[wbase + 4];
    const float* b2b = (const float*)d_in[wbase + 5];
    const float* b3w = (const float*)d_in[wbase + 6];
    const float* b3b = (const float*)d_in[wbase + 7];
    const float* fw = (const float*)d_in[wbase + 8];
    const float* fb = (const float*)d_in[wbase + 9];

    float* out = (float*)d_out;
    float* Mout = out + BB * CC * HWP;

    cudaFuncSetAttribute(conv3x3_k<0>, cudaFuncAttributeMaxDynamicSharedMemorySize, CONV_SMEM);
    cudaFuncSetAttribute(conv3x3_k<1>, cudaFuncAttributeMaxDynamicSharedMemorySize, CONV_SMEM);
    cudaFuncSetAttribute(qsr_k, cudaFuncAttributeMaxDynamicSharedMemorySize, QSR_SMEM);

    prep_k<<<192, 256>>>(rb_w1, rb_w2, b1w, b2w, b3w);

    dim3 g3(WW / 32, HH / 8, 8);
    conv3x3_k<0><<<g3, 256, CONV_SMEM>>>(xl, xr);
    conv3x3_k<1><<<g3, 256, CONV_SMEM>>>(xl, xr);

    qsr_k<<<dim3(BB * HWP / 256, 3), 256, QSR_SMEM>>>(b1b, b2b, b3b);

    attn_k<<<BB * HWP / 8, 256>>>(xxs, yys, Mout);

    fuse_k<<<dim3(HWP / 256, BB), 256>>>(xl, fw, fb, out);
}